// round 17
// baseline (speedup 1.0000x reference)
#include <cuda_runtime.h>
#include <math.h>

// ---------------------------------------------------------------------------
// Kalman filter + RTS smoother, T=4096, DZ=DX=64.
// Covariance chains truncated at the fp32 fixed point (NC forward steps,
// NTAIL+NC backward).  Steady-state means recursions use COMPOSED operators:
//   forward : fm = M fm' + K y + n,  M = A - K HA, n = b - K bh
//   backward: sm = W fm + C sm' - wb, W = I - C A,  wb = C b
// -> one fused matvec + one barrier per step, warp-specialized groups.
// ---------------------------------------------------------------------------

static constexpr int TT    = 4096;
static constexpr int NC    = 96;              // forward covariance steps computed exactly
static constexpr int NTAIL = 96;              // backward smoother tail steps computed exactly
static constexpr int TB    = TT - 1 - NTAIL;  // tail region is [TB, T-2]
static constexpr int NN    = 64 * 64;
static constexpr int ROW   = 68;              // padded smem row stride
static constexpr int MAT   = 64 * ROW;
static constexpr int NT    = 256;             // threads for covariance kernels

// ----- device scratch (static device globals: allowed; no allocation) -----
__device__ float g_pP  [(size_t)NC * NN];
__device__ float g_AP  [(size_t)NC * NN];
__device__ float g_fP  [(size_t)NC * NN];
__device__ float g_K   [(size_t)NC * NN];
__device__ float g_Sinv[(size_t)NC * NN];
__device__ float g_C   [(size_t)NC * NN];
__device__ float g_CT  [(size_t)NC * NN];
__device__ float g_logdet[NC];
__device__ float g_HA[NN];
__device__ float g_bh[64];
__device__ float g_M[NN];      // steady forward operator A - K HA
__device__ float g_n[64];      // steady forward offset  b - K bh
__device__ float g_W[NN];      // steady backward operator I - C A
__device__ float g_wb[64];     // steady backward offset  C b
__device__ float g_pm[(size_t)TT * 64];   // only t < NC used
__device__ float g_fm[(size_t)TT * 64];
__device__ float g_sPbss[NN];
__device__ int   g_ready;   // forward-chain progress flag (monotone per run)

// ----- packed f32x2 helpers (sm_103a) --------------------------------------
#define FMA2(d, a, b, c) \
    asm("fma.rn.f32x2 %0, %1, %2, %3;" : "=l"(d) : "l"(a), "l"(b), "l"(c))
#define PACK2(d, lo, hi) \
    asm("mov.b64 %0, {%1, %2};" : "=l"(d) : "r"(lo), "r"(hi))
#define UNPACK2(lo, hi, v) \
    asm("mov.b64 {%0, %1}, %2;" : "=r"(lo), "=r"(hi) : "l"(v))

// ---------------------------------------------------------------------------
// 64x64 GEMM, 256 threads, 4x4 register tiles, f32x2 packed FMAs.
// ---------------------------------------------------------------------------
template<int MODE, bool TAS, int CS, int DS>
__device__ __forceinline__ void gemm64(float* C, const float* A, const float* B,
                                       const float* D, float* G = nullptr,
                                       float* CT = nullptr)
{
    __syncthreads();
    const int tid = threadIdx.x;
    const int r0 = (tid >> 4) << 2;
    const int c0 = (tid & 15) << 2;
    unsigned long long acc[4][2];
    #pragma unroll
    for (int i = 0; i < 4; i++) { acc[i][0] = 0ull; acc[i][1] = 0ull; }

    #pragma unroll 8
    for (int k = 0; k < 64; k++) {
        float a0, a1, a2, a3;
        if (TAS) {
            a0 = A[(r0 + 0) * ROW + k];
            a1 = A[(r0 + 1) * ROW + k];
            a2 = A[(r0 + 2) * ROW + k];
            a3 = A[(r0 + 3) * ROW + k];
        } else {
            const float4 v = *(const float4*)(A + k * ROW + r0);
            a0 = v.x; a1 = v.y; a2 = v.z; a3 = v.w;
        }
        const unsigned long long b01 = *(const unsigned long long*)(B + k * ROW + c0);
        const unsigned long long b23 = *(const unsigned long long*)(B + k * ROW + c0 + 2);
        unsigned long long aa;
        unsigned int u;
        u = __float_as_uint(a0); PACK2(aa, u, u);
        FMA2(acc[0][0], aa, b01, acc[0][0]); FMA2(acc[0][1], aa, b23, acc[0][1]);
        u = __float_as_uint(a1); PACK2(aa, u, u);
        FMA2(acc[1][0], aa, b01, acc[1][0]); FMA2(acc[1][1], aa, b23, acc[1][1]);
        u = __float_as_uint(a2); PACK2(aa, u, u);
        FMA2(acc[2][0], aa, b01, acc[2][0]); FMA2(acc[2][1], aa, b23, acc[2][1]);
        u = __float_as_uint(a3); PACK2(aa, u, u);
        FMA2(acc[3][0], aa, b01, acc[3][0]); FMA2(acc[3][1], aa, b23, acc[3][1]);
    }

    #pragma unroll
    for (int i = 0; i < 4; i++) {
        #pragma unroll
        for (int p = 0; p < 2; p++) {
            unsigned int ulo, uhi;
            UNPACK2(ulo, uhi, acc[i][p]);
            float v0 = __uint_as_float(ulo);
            float v1 = __uint_as_float(uhi);
            const int r = r0 + i, ca = c0 + 2 * p, cb = ca + 1;
            if (MODE == 1) { v0 += D[r * DS + ca]; v1 += D[r * DS + cb]; }
            if (MODE == 2) { v0 = D[r * DS + ca] - v0; v1 = D[r * DS + cb] - v1; }
            C[r * CS + ca] = v0;
            C[r * CS + cb] = v1;
            if (G)  { G[r * 64 + ca] = v0; G[r * 64 + cb] = v1; }
            if (CT) { CT[ca * 64 + r] = v0; CT[cb * 64 + r] = v1; }
        }
    }
    __syncthreads();
}

// ----- stride-converting float4 copies (NT threads) -------------------------
__device__ __forceinline__ void g2s(float* dst, const float* src) // gmem(64)->smem(ROW)
{
    for (int idx = threadIdx.x; idx < 1024; idx += NT) {
        const int r = idx >> 4, c4 = idx & 15;
        ((float4*)dst)[r * (ROW / 4) + c4] = ((const float4*)src)[r * 16 + c4];
    }
    __syncthreads();
}
__device__ __forceinline__ void s2g(float* dst, const float* src) // smem(ROW)->gmem(64)
{
    for (int idx = threadIdx.x; idx < 1024; idx += NT) {
        const int r = idx >> 4, c4 = idx & 15;
        ((float4*)dst)[r * 16 + c4] = ((const float4*)src)[r * (ROW / 4) + c4];
    }
    __syncthreads();
}

// ---------------------------------------------------------------------------
// In-place LDL^T of SPD 64x64; one barrier per round.
// ---------------------------------------------------------------------------
__device__ void chol_ldl(float* S, float* dv, float* rdv)
{
    __shared__ float s_rd[64];
    const int tid = threadIdx.x;
    if (tid == 0) {
        const float d0 = S[0];
        dv[0] = d0;
        const float r = __frcp_rn(d0);
        rdv[0] = r; s_rd[0] = r;
    }
    __syncthreads();
    for (int k = 0; k < 63; k++) {
        const float rd = s_rd[k];
        const int i = k + 1 + (tid >> 2);
        if (i < 64) {
            const float f = S[i * ROW + k] * rd;
            const int j0 = (tid & 3) * 16;
            #pragma unroll
            for (int jj = 0; jj < 16; jj++) {
                const int j = j0 + jj;
                if (j > k && j <= i) {
                    const float nv = S[i * ROW + j] - f * S[j * ROW + k];
                    S[i * ROW + j] = nv;
                    if (i == k + 1 && j == k + 1) {
                        dv[k + 1] = nv;
                        const float r1 = __frcp_rn(nv);
                        rdv[k + 1] = r1; s_rd[k + 1] = r1;
                    }
                }
            }
        }
        __syncthreads();
    }
}

// X = Linv for L = L' diag(sqrt(d)):  X = diag(d^{-1/2}) L'^{-1}.
__device__ void triinv_scaled(float* X, const float* S, const float* rdv,
                              const float* dv)
{
    const int tid = threadIdx.x;
    for (int idx = tid; idx < MAT; idx += NT) X[idx] = 0.0f;
    __syncthreads();
    if (tid < 64) X[tid * ROW + tid] = 1.0f;
    __syncthreads();
    for (int i = 0; i < 64; i++) {
        const int m = i + 1 + (tid >> 2);
        if (m < 64) {
            const float lmi = S[m * ROW + i] * rdv[i];
            const int j0 = (tid & 3) * 16;
            #pragma unroll
            for (int jj = 0; jj < 16; jj++) {
                const int j = j0 + jj;
                if (j <= i) X[m * ROW + j] -= lmi * X[i * ROW + j];
            }
        }
        __syncthreads();
    }
    {
        const int r = tid >> 2;
        const float sc = rsqrtf(dv[r]);
        const int j0 = (tid & 3) * 16;
        #pragma unroll
        for (int jj = 0; jj < 16; jj++) X[r * ROW + j0 + jj] *= sc;
    }
    __syncthreads();
}

// ---------------------------------------------------------------------------
// Kernel 1: forward covariance chain (NC steps, single CTA).  Gains deferred.
// Epilogue composes M = A - K HA, n = b - K bh; sentinel g_ready = NC+1.
// ---------------------------------------------------------------------------
__global__ void __launch_bounds__(NT)
k_cov_forward(const float* __restrict__ Ag, const float* __restrict__ bg,
              const float* __restrict__ Qg, const float* __restrict__ Hg,
              const float* __restrict__ cg, const float* __restrict__ Rg,
              const float* __restrict__ prior_cov)
{
    extern __shared__ float sm[];
    float* AsT = sm + 0 * MAT;
    float* As  = sm + 1 * MAT;
    float* HsT = sm + 2 * MAT;
    float* Qs  = sm + 3 * MAT;
    float* Rs  = sm + 4 * MAT;
    float* M0  = sm + 5 * MAT;   // fP (carried)
    float* M1  = sm + 6 * MAT;   // AP / HP
    float* M2  = sm + 7 * MAT;   // pP
    float* M3  = sm + 8 * MAT;   // LDL factor
    float* M4  = sm + 9 * MAT;   // Linv / K
    float* M5  = sm + 10 * MAT;  // Sinv
    __shared__ float dv[64], rdv[64], sbhv[64];

    const int tid = threadIdx.x;
    for (int idx = tid; idx < NN; idx += NT) {
        const int r = idx >> 6, cc = idx & 63;
        const float va = Ag[idx];
        AsT[cc * ROW + r] = va;
        As[r * ROW + cc]  = va;
        HsT[cc * ROW + r] = Hg[idx];
    }
    __syncthreads();
    g2s(Qs, Qg);
    g2s(Rs, Rg);

    // one-time precompute for the means kernel: HA = H @ A, bh = H b + c
    gemm64<0, false, 64, ROW>(g_HA, HsT, As, nullptr);
    if (tid < 64) {
        float s = cg[tid];
        #pragma unroll 8
        for (int k = 0; k < 64; k++) s += Hg[tid * 64 + k] * bg[k];
        g_bh[tid] = s;
        sbhv[tid] = s;
    }
    __syncthreads();

    for (int t = 0; t < NC; t++) {
        if (t == 0) {
            g2s(M2, prior_cov);                                         // pP_0
        } else {
            gemm64<0, false, ROW, ROW>(M1, AsT, M0, nullptr,
                                       g_AP + (size_t)t * NN);          // AP = A fP
            gemm64<1, true,  ROW, ROW>(M2, M1, AsT, Qs,
                                       g_pP + (size_t)t * NN);          // pP = AP A^T + Q
        }
        gemm64<0, false, ROW, ROW>(M1, HsT, M2, nullptr);               // HP = H pP
        gemm64<1, true,  ROW, ROW>(M3, M1, HsT, Rs);                    // S = HP H^T + R
        chol_ldl(M3, dv, rdv);
        if (tid < 32) {                                                 // logdet
            float v = __logf(dv[tid]) + __logf(dv[tid + 32]);
            #pragma unroll
            for (int o = 16; o > 0; o >>= 1) v += __shfl_down_sync(0xffffffffu, v, o);
            if (tid == 0) g_logdet[t] = 0.5f * v;
        }
        triinv_scaled(M4, M3, rdv, dv);                                 // Linv
        gemm64<0, false, ROW, ROW>(M5, M4, M4, nullptr,
                                   g_Sinv + (size_t)t * NN);            // Sinv
        gemm64<0, false, ROW, ROW>(M4, M1, M5, nullptr,
                                   g_K + (size_t)t * NN);               // K = HP^T Sinv
        gemm64<2, true,  ROW, ROW>(M0, M4, M1, M2,
                                   g_fP + (size_t)t * NN);              // fP = pP - K HP
        __threadfence();
        __syncthreads();
        if (tid == 0) atomicExch(&g_ready, t + 1);
    }

    // ---- epilogue: compose steady forward operator (M4 holds steady K) ----
    gemm64<0, false, ROW, ROW>(M1, HsT, As, nullptr);                   // HA (smem)
    gemm64<2, true,  64,  ROW>(g_M, M4, M1, As);                        // M = A - K HA
    if (tid < 64) {
        float s = bg[tid];
        #pragma unroll 8
        for (int k = 0; k < 64; k++) s -= M4[tid * ROW + k] * sbhv[k];
        g_n[tid] = s;                                                   // n = b - K bh
    }
    __threadfence();
    __syncthreads();
    if (tid == 0) atomicExch(&g_ready, NC + 1);
}

// ---------------------------------------------------------------------------
// Kernel 1b: smoother gains, fully parallel across time (NC-1 CTAs).
// CTA NC-2 additionally composes W = I - C_ss A and wb = C_ss b.
// ---------------------------------------------------------------------------
__global__ void __launch_bounds__(NT)
k_gains(const float* __restrict__ Ag, const float* __restrict__ bg)
{
    extern __shared__ float sm[];
    float* APs = sm + 0 * MAT;
    float* M3  = sm + 1 * MAT;
    float* X   = sm + 2 * MAT;
    float* Pi  = sm + 3 * MAT;
    __shared__ float dv[64], rdv[64];
    const int tid = threadIdx.x;
    const int t = blockIdx.x + 1;

    g2s(APs, g_AP + (size_t)t * NN);
    g2s(M3,  g_pP + (size_t)t * NN);
    chol_ldl(M3, dv, rdv);
    triinv_scaled(X, M3, rdv, dv);
    gemm64<0, false, ROW, ROW>(Pi, X, X, nullptr);                      // pPinv
    gemm64<0, false, 64,  ROW>(g_C + (size_t)(t - 1) * NN, APs, Pi,
                               nullptr, nullptr,
                               g_CT + (size_t)(t - 1) * NN);            // C = AP^T pPinv

    if (blockIdx.x == NC - 2) {
        // steady backward operator: W = I - C A, wb = C b
        g2s(M3, g_CT + (size_t)(NC - 2) * NN);      // CT (own writes, same SM)
        g2s(APs, Ag);                               // A
        for (int idx = tid; idx < MAT; idx += NT) X[idx] = 0.0f;
        __syncthreads();
        if (tid < 64) X[tid * ROW + tid] = 1.0f;
        __syncthreads();
        gemm64<2, false, 64, ROW>(g_W, M3, APs, X); // W = I - C A
        if (tid < 64) {
            float s = 0.0f;
            #pragma unroll 8
            for (int k = 0; k < 64; k++)
                s += g_C[(size_t)(NC - 2) * NN + tid * 64 + k] * bg[k];
            g_wb[tid] = s;
        }
    }
}

// ---------------------------------------------------------------------------
// Kernel 2: forward means + log-likelihood, CONCURRENT with kernel 1
// (flag-paced exact path for t<NC), then composed steady recursion:
// one barrier/step, warp groups {fm, r, q-pipeline}, obs prefetched.
// ---------------------------------------------------------------------------
__global__ void __launch_bounds__(256)
k_means_forward(const float* __restrict__ obs, const float* __restrict__ Ag,
                const float* __restrict__ bg, const float* __restrict__ Hg,
                const float* __restrict__ cg, const float* __restrict__ pm0,
                float* __restrict__ out_ll)
{
    extern __shared__ float smf[];
    float* sAH = smf;                  // old path: A rows 0-63, HA rows 64-127
    float* sM  = smf + 128 * ROW;      // steady M
    float* sK  = sM + 64 * ROW;        // steady K
    float* sHA = sK + 64 * ROW;        // steady HA
    float* sSv = sHA + 64 * ROW;       // steady Sinv
    __shared__ float xb[2][64], ybuf[2][64], rbuf[2][64];
    __shared__ float o1[64], rres[64], sbh[128], sn[64], wsum[4];
    __shared__ double qws[2];
    const int tid = threadIdx.x;
    const int row = tid >> 1, h = tid & 1;
    const int lane = tid & 31, wid = tid >> 5;
    double ll = 0.0;
    const float llc = -58.81206612509907f;   // -0.5 * 64 * log(2*pi)

    // wait for producer step 1 (g_HA / g_bh ready), then stage old-path mats
    if (tid == 0) while (atomicAdd(&g_ready, 0) < 1) __nanosleep(200);
    __syncthreads();
    for (int idx = tid; idx < 2 * NN; idx += 256) {
        const int r = idx >> 6, c = idx & 63;
        sAH[r * ROW + c] = (r < 64) ? Ag[idx] : __ldcg(&g_HA[(size_t)(r - 64) * 64 + c]);
    }
    if (tid < 64) sbh[tid] = bg[tid];
    else if (tid < 128) sbh[tid] = __ldcg(&g_bh[tid - 64]);
    if (tid < 64) xb[0][tid] = pm0[tid];
    __syncthreads();

    // ======================= exact path: t in [0, NC) ======================
    for (int t = 0; t < NC; t++) {
        if (t > 0) {                           // pace behind the producer
            if (tid == 0)
                while (atomicAdd(&g_ready, 0) < t + 1) __nanosleep(200);
            __syncthreads();
        }
        if (t == NC - 1 && tid < 64)           // bootstrap steady obs buffer
            ybuf[0][tid] = __ldg(&obs[(size_t)NC * 64 + tid]);

        // ---- phase 1: rows<64 -> pm ; rows>=64 -> yhat, rres -------------
        if (t == 0) {
            if (row < 64) {
                if (h == 0) { o1[row] = xb[0][row]; g_pm[row] = xb[0][row]; }
            } else {
                const float ob = __ldg(&obs[row - 64]);
                const float4* M4 = (const float4*)(Hg + (size_t)(row - 64) * 64 + h * 32);
                float s = 0.0f;
                #pragma unroll
                for (int q = 0; q < 8; q++) {
                    const float4 v = M4[q];
                    const int k = h * 32 + q * 4;
                    s += v.x * xb[0][k] + v.y * xb[0][k + 1] + v.z * xb[0][k + 2] + v.w * xb[0][k + 3];
                }
                s += __shfl_down_sync(0xffffffffu, s, 1, 2);
                if (h == 0) rres[row - 64] = ob - (s + __ldg(&cg[row - 64]));
            }
        } else {
            float ob = 0.0f;
            if (row >= 64 && h == 0) ob = __ldg(&obs[(size_t)t * 64 + (row - 64)]);
            const float4* M4 = (const float4*)(sAH + row * ROW + h * 32);
            float s = 0.0f;
            #pragma unroll
            for (int q = 0; q < 8; q++) {
                const float4 v = M4[q];
                const int k = h * 32 + q * 4;
                s += v.x * xb[0][k] + v.y * xb[0][k + 1] + v.z * xb[0][k + 2] + v.w * xb[0][k + 3];
            }
            s += __shfl_down_sync(0xffffffffu, s, 1, 2);
            if (h == 0) {
                const float sv = s + sbh[row];
                if (row < 64) { o1[row] = sv; g_pm[(size_t)t * 64 + row] = sv; }
                else          rres[row - 64] = ob - sv;
            }
        }
        __syncthreads();

        // ---- phase 2: rows<64 -> r^T Sinv r ; rows>=64 -> fm -------------
        float s2 = 0.0f;
        {
            const float* Mr = (row < 64)
                ? (g_Sinv + (size_t)t * NN + row * 64)
                : (g_K + (size_t)t * NN + (size_t)(row - 64) * 64);
            const float4* M4 = (const float4*)(Mr + h * 32);
            #pragma unroll
            for (int q = 0; q < 8; q++) {
                const float4 v = M4[q];
                const int k = h * 32 + q * 4;
                s2 += v.x * rres[k] + v.y * rres[k + 1] + v.z * rres[k + 2] + v.w * rres[k + 3];
            }
        }
        s2 += __shfl_down_sync(0xffffffffu, s2, 1, 2);

        if (row < 64) {
            float contrib = (h == 0) ? rres[row] * s2 : 0.0f;
            #pragma unroll
            for (int o = 16; o > 0; o >>= 1)
                contrib += __shfl_down_sync(0xffffffffu, contrib, o);
            if (lane == 0) wsum[wid] = contrib;
        } else if (h == 0) {
            const float f = o1[row - 64] + s2;
            xb[0][row - 64] = f;
            g_fm[(size_t)t * 64 + (row - 64)] = f;
        }
        __syncthreads();

        if (tid == 0)
            ll += (double)(llc - 0.5f * (wsum[0] + wsum[1] + wsum[2] + wsum[3]));
    }

    // ---------------- stage composed operators (wait for sentinel) ---------
    if (tid == 0) while (atomicAdd(&g_ready, 0) < NC + 1) __nanosleep(200);
    __syncthreads();
    for (int idx = tid; idx < NN; idx += 256) {
        const int r = idx >> 6, c = idx & 63;
        sM [r * ROW + c] = __ldcg(&g_M[idx]);
        sK [r * ROW + c] = __ldcg(&g_K[(size_t)(NC - 1) * NN + idx]);
        sHA[r * ROW + c] = __ldcg(&g_HA[idx]);
        sSv[r * ROW + c] = __ldcg(&g_Sinv[(size_t)(NC - 1) * NN + idx]);
    }
    if (tid < 64) sn[tid] = __ldcg(&g_n[tid]);
    __syncthreads();

    // ================= steady path: t in [NC, TT), 1 barrier ===============
    double qacc = 0.0;
    for (int t = NC; t < TT; t++) {
        const int cur = t & 1, nxt = cur ^ 1;
        if (tid < 128) {
            // fm = M x + K y + n  (2 threads/row, halves select M/x vs K/y)
            const float* vec = h ? ybuf[cur] : xb[cur];
            const float4* M4 = (const float4*)((h ? sK : sM) + row * ROW);
            float s = 0.0f;
            #pragma unroll
            for (int p = 0; p < 16; p++) {
                const float4 v = M4[p];
                const int k = p * 4;
                s += v.x * vec[k] + v.y * vec[k + 1] + v.z * vec[k + 2] + v.w * vec[k + 3];
            }
            s += __shfl_down_sync(0xffffffffu, s, 1, 2);
            if (h == 0) {
                const float f = s + sn[row];
                xb[nxt][row] = f;
                g_fm[(size_t)t * 64 + row] = f;
            }
        } else if (tid < 192) {
            // r_t = y - HA x - bh
            const int r = tid - 128;
            const float4* M4 = (const float4*)(sHA + r * ROW);
            const float* xc = xb[cur];
            float s = 0.0f;
            #pragma unroll
            for (int p = 0; p < 16; p++) {
                const float4 v = M4[p];
                const int k = p * 4;
                s += v.x * xc[k] + v.y * xc[k + 1] + v.z * xc[k + 2] + v.w * xc[k + 3];
            }
            rbuf[cur][r] = ybuf[cur][r] - s - sbh[64 + r];
        } else {
            // prefetch obs[t+1]; q_{t-1} = r'^T Sinv r' (one-step lag)
            const int r = tid - 192;
            if (t < TT - 1) ybuf[nxt][r] = __ldg(&obs[(size_t)(t + 1) * 64 + r]);
            if (t > NC) {
                const float* rp = rbuf[nxt];            // r_{t-1}
                const float4* M4 = (const float4*)(sSv + r * ROW);
                float z = 0.0f;
                #pragma unroll
                for (int p = 0; p < 16; p++) {
                    const float4 v = M4[p];
                    const int k = p * 4;
                    z += v.x * rp[k] + v.y * rp[k + 1] + v.z * rp[k + 2] + v.w * rp[k + 3];
                }
                qacc += (double)(rp[r] * z);
            }
        }
        __syncthreads();
    }

    // drain q for t = TT-1, reduce q accumulators
    if (tid >= 192) {
        const int r = tid - 192;
        const float* rp = rbuf[(TT - 1) & 1];
        const float4* M4 = (const float4*)(sSv + r * ROW);
        float z = 0.0f;
        #pragma unroll
        for (int p = 0; p < 16; p++) {
            const float4 v = M4[p];
            const int k = p * 4;
            z += v.x * rp[k] + v.y * rp[k + 1] + v.z * rp[k + 2] + v.w * rp[k + 3];
        }
        qacc += (double)(rp[r] * z);
        double v = qacc;
        #pragma unroll
        for (int o = 16; o > 0; o >>= 1) v += __shfl_down_sync(0xffffffffu, v, o);
        if (lane == 0) qws[wid - 6] = v;
    }
    __syncthreads();

    if (tid == 0) {
        double lds = 0.0;
        for (int t = 0; t < NC - 1; t++) lds += (double)__ldcg(&g_logdet[t]);
        lds += (double)(TT - (NC - 1)) * (double)__ldcg(&g_logdet[NC - 1]);
        const double llc_d = -58.81206612509905;
        *out_ll = (float)(ll + (double)(TT - NC) * llc_d
                          - 0.5 * (qws[0] + qws[1]) - lds);
    }
}

// ---------------------------------------------------------------------------
// Kernel 3: backward smoothed covariances.  grid=2 (tail | doubling+head).
// ---------------------------------------------------------------------------
__global__ void __launch_bounds__(NT)
k_cov_backward(float* __restrict__ out_cov)
{
    extern __shared__ float sm[];
    float* sP  = sm + 0 * MAT;
    float* Cst = sm + 1 * MAT;
    float* Dm  = sm + 2 * MAT;
    float* Em  = sm + 3 * MAT;
    float* pPs = sm + 4 * MAT;
    float* Tm  = sm + 5 * MAT;
    const int tid = threadIdx.x;

    const float* fPs = g_fP + (size_t)(NC - 1) * NN;

    if (blockIdx.x == 0) {
        g2s(sP, fPs);
        s2g(out_cov + (size_t)(TT - 1) * NN, sP);
        g2s(Cst, g_CT + (size_t)(NC - 2) * NN);
        g2s(pPs, g_pP + (size_t)(NC - 1) * NN);
        for (int t = TT - 2; t >= TB; t--) {
            for (int idx = tid; idx < MAT / 4; idx += NT)
                ((float4*)Dm)[idx] = make_float4(
                    ((const float4*)sP)[idx].x - ((const float4*)pPs)[idx].x,
                    ((const float4*)sP)[idx].y - ((const float4*)pPs)[idx].y,
                    ((const float4*)sP)[idx].z - ((const float4*)pPs)[idx].z,
                    ((const float4*)sP)[idx].w - ((const float4*)pPs)[idx].w);
            gemm64<0, false, ROW, ROW>(Em, Cst, Dm, nullptr);
            gemm64<1, true,  ROW, 64 >(sP, Em, Cst, fPs);
            s2g(out_cov + (size_t)t * NN, sP);
        }
    } else {
        g2s(Cst, g_CT + (size_t)(NC - 2) * NN);
        g2s(pPs, g_pP + (size_t)(NC - 1) * NN);
        gemm64<0, false, ROW, ROW>(Tm, Cst, pPs, nullptr);
        gemm64<2, true,  ROW, 64 >(sP, Tm, Cst, fPs);
        float* Mt = Cst;
        float* Sq = Em;
        for (int it = 0; it < 8; it++) {
            gemm64<0, false, ROW, ROW>(Tm, Mt, sP, nullptr);
            gemm64<1, true,  ROW, ROW>(sP, Tm, Mt, sP);
            gemm64<0, true,  ROW, ROW>(Sq, Mt, Mt, nullptr);
            float* tmp = Mt; Mt = Sq; Sq = tmp;
        }
        s2g(g_sPbss, sP);

        for (int t = NC - 1; t >= 0; t--) {
            const int tcC = (t < NC - 1) ? t : (NC - 2);
            const int tcn = (t + 1 < NC) ? (t + 1) : (NC - 1);
            g2s(Sq, g_CT + (size_t)tcC * NN);
            const float4* gpP = (const float4*)(g_pP + (size_t)tcn * NN);
            for (int idx = tid; idx < 1024; idx += NT) {
                const int r = idx >> 4, c4 = idx & 15;
                const float4 a = ((const float4*)sP)[r * (ROW / 4) + c4];
                const float4 p = gpP[r * 16 + c4];
                ((float4*)Dm)[r * (ROW / 4) + c4] =
                    make_float4(a.x - p.x, a.y - p.y, a.z - p.z, a.w - p.w);
            }
            gemm64<0, false, ROW, ROW>(Tm, Sq, Dm, nullptr);
            gemm64<1, true,  ROW, 64 >(sP, Tm, Sq, g_fP + (size_t)t * NN);
            s2g(out_cov + (size_t)t * NN, sP);
        }
    }
}

// Kernel 4: fill the converged middle region [NC, TB) with the steady value.
__global__ void k_fill(float* __restrict__ out_cov)
{
    const size_t start = (size_t)NC * NN;
    const size_t end   = (size_t)TB * NN;
    const size_t stride = (size_t)gridDim.x * blockDim.x;
    for (size_t i = start + (size_t)blockIdx.x * blockDim.x + threadIdx.x;
         i < end; i += stride)
        out_cov[i] = g_sPbss[i & (NN - 1)];
}

// ---------------------------------------------------------------------------
// Kernel 5: backward smoothed means.  Steady region: composed single matvec
// sm = W fm + C sm' - wb, 1 barrier/step, fm prefetched.  Head: exact.
// ---------------------------------------------------------------------------
__global__ void __launch_bounds__(256)
k_means_backward(float* __restrict__ out_sm)
{
    extern __shared__ float smb[];
    float* sW = smb;             // 64*ROW
    float* sC = smb + 64 * ROW;  // 64*ROW
    __shared__ float fmv[2][64], smv[2][64], d[64], qwb[64];
    const int tid = threadIdx.x;
    const int row = tid >> 2, q = tid & 3;

    for (int idx = tid; idx < NN; idx += 256) {
        const int r = idx >> 6, c = idx & 63;
        sW[r * ROW + c] = __ldg(&g_W[idx]);
        sC[r * ROW + c] = __ldg(&g_C[(size_t)(NC - 2) * NN + idx]);
    }
    float pref = 0.0f;
    if (tid < 64) {
        qwb[tid] = __ldg(&g_wb[tid]);
        const float v = __ldg(&g_fm[(size_t)(TT - 1) * 64 + tid]);
        smv[0][tid] = v;                               // (TT-2)&1 == 0
        out_sm[(size_t)(TT - 1) * 64 + tid] = v;
        fmv[0][tid] = __ldg(&g_fm[(size_t)(TT - 2) * 64 + tid]);
        pref = __ldg(&g_fm[(size_t)(TT - 3) * 64 + tid]);
    }
    __syncthreads();

    // steady region: t = TT-2 .. NC-1
    for (int t = TT - 2; t >= NC - 1; t--) {
        const int cur = t & 1, nxt = cur ^ 1;
        const float* vec = (q < 2) ? fmv[cur] : smv[cur];
        const float4* M4 = (const float4*)(((q < 2) ? sW : sC) + row * ROW + (q & 1) * 32);
        float s = 0.0f;
        #pragma unroll
        for (int p = 0; p < 8; p++) {
            const float4 v = M4[p];
            const int k = (q & 1) * 32 + p * 4;
            s += v.x * vec[k] + v.y * vec[k + 1] + v.z * vec[k + 2] + v.w * vec[k + 3];
        }
        if (tid < 64) {
            fmv[nxt][tid] = pref;                      // fm_{t-1} for next step
            if (t >= 2) pref = __ldg(&g_fm[(size_t)(t - 2) * 64 + tid]);
        }
        s += __shfl_down_sync(0xffffffffu, s, 2, 4);
        s += __shfl_down_sync(0xffffffffu, s, 1, 4);
        if (q == 0) {
            const float nv = s - qwb[row];
            smv[nxt][row] = nv;
            out_sm[(size_t)t * 64 + row] = nv;
        }
        __syncthreads();
    }

    // head region: t = NC-2 .. 0 (exact per-t C, stored pm)
    for (int t = NC - 2; t >= 0; t--) {
        const int cur = t & 1, nxt = cur ^ 1;
        if (tid < 64)
            d[tid] = smv[cur][tid] - __ldg(&g_pm[(size_t)(t + 1) * 64 + tid]);
        __syncthreads();
        const float4* M4 = (const float4*)(g_C + (size_t)t * NN + row * 64 + q * 16);
        float s = 0.0f;
        #pragma unroll
        for (int p = 0; p < 4; p++) {
            const float4 v = M4[p];
            const int k = q * 16 + p * 4;
            s += v.x * d[k] + v.y * d[k + 1] + v.z * d[k + 2] + v.w * d[k + 3];
        }
        s += __shfl_down_sync(0xffffffffu, s, 2, 4);
        s += __shfl_down_sync(0xffffffffu, s, 1, 4);
        if (q == 0) {
            const float nv = __ldg(&g_fm[(size_t)t * 64 + row]) + s;
            smv[nxt][row] = nv;
            out_sm[(size_t)t * 64 + row] = nv;
        }
        __syncthreads();
    }
}

// ---------------------------------------------------------------------------
extern "C" void kernel_launch(void* const* d_in, const int* in_sizes, int n_in,
                              void* d_out, int out_size)
{
    (void)in_sizes; (void)n_in; (void)out_size;
    const float* obs = (const float*)d_in[0];
    const float* A   = (const float*)d_in[1];
    const float* b   = (const float*)d_in[2];
    const float* Q   = (const float*)d_in[3];
    const float* H   = (const float*)d_in[4];
    const float* c   = (const float*)d_in[5];
    const float* R   = (const float*)d_in[6];
    const float* pm0 = (const float*)d_in[7];
    const float* pP0 = (const float*)d_in[8];

    float* out     = (float*)d_out;
    float* out_sm  = out;                                        // [T,64]
    float* out_cov = out + (size_t)TT * 64;                      // [T,64,64]
    float* out_ll  = out + (size_t)TT * 64 + (size_t)TT * NN;    // scalar

    static cudaStream_t s2 = nullptr;
    static cudaEvent_t ev0, evG, evE;
    if (!s2) {
        cudaStreamCreateWithFlags(&s2, cudaStreamNonBlocking);
        cudaEventCreateWithFlags(&ev0, cudaEventDisableTiming);
        cudaEventCreateWithFlags(&evG, cudaEventDisableTiming);
        cudaEventCreateWithFlags(&evE, cudaEventDisableTiming);
        cudaFuncSetAttribute((const void*)k_cov_forward,
                             cudaFuncAttributeMaxDynamicSharedMemorySize,
                             11 * MAT * (int)sizeof(float));
        cudaFuncSetAttribute((const void*)k_gains,
                             cudaFuncAttributeMaxDynamicSharedMemorySize,
                             4 * MAT * (int)sizeof(float));
        cudaFuncSetAttribute((const void*)k_cov_backward,
                             cudaFuncAttributeMaxDynamicSharedMemorySize,
                             6 * MAT * (int)sizeof(float));
        cudaFuncSetAttribute((const void*)k_means_forward,
                             cudaFuncAttributeMaxDynamicSharedMemorySize,
                             (128 * ROW + 4 * 64 * ROW) * (int)sizeof(float));
        cudaFuncSetAttribute((const void*)k_means_backward,
                             cudaFuncAttributeMaxDynamicSharedMemorySize,
                             2 * MAT * (int)sizeof(float));
    }

    // Fork: means_forward runs concurrently with cov_forward (flag-paced).
    cudaEventRecord(ev0, 0);
    cudaStreamWaitEvent(s2, ev0, 0);
    k_means_forward<<<1, 256, (128 * ROW + 4 * 64 * ROW) * sizeof(float), s2>>>(
        obs, A, b, H, c, pm0, out_ll);

    k_cov_forward<<<1, NT, 11 * MAT * sizeof(float)>>>(A, b, Q, H, c, R, pP0);
    k_gains<<<NC - 1, NT, 4 * MAT * sizeof(float)>>>(A, b);
    cudaEventRecord(evG, 0);
    k_cov_backward<<<2, NT, 6 * MAT * sizeof(float)>>>(out_cov);
    k_fill<<<1024, 256>>>(out_cov);

    cudaStreamWaitEvent(s2, evG, 0);          // means_backward needs g_C/g_W
    k_means_backward<<<1, 256, 2 * MAT * sizeof(float), s2>>>(out_sm);

    cudaEventRecord(evE, s2);                 // join
    cudaStreamWaitEvent(0, evE, 0);
}